// round 1
// baseline (speedup 1.0000x reference)
#include <cuda_runtime.h>
#include <math.h>

// Problem constants (from reference): N=50000, E=800000, K=16, D=128, H=8, DH=16
#define NMAX 50000
#define EMAX 800000
#define SCALE_Q 0.08838834764831845f   // 128^-0.5

// -------- scratch (device globals; no allocation in kernel_launch) --------
__device__ float g_xln[(size_t)NMAX * 128];     // LN output (reused twice)
__device__ float g_qkv[(size_t)NMAX * 384];     // q(0..127)|k(128..255)|v(256..383)
__device__ float g_scores[(size_t)EMAX * 8];    // per-edge per-head scores
__device__ float g_attn[(size_t)NMAX * 128];    // attention output
__device__ float g_x2[(size_t)NMAX * 128];      // residual stream after attn
__device__ float g_hid[(size_t)NMAX * 512];     // FFN hidden

// ---------------------------------------------------------------------------
// LayerNorm: one row per warp (32 lanes x float4)
// ---------------------------------------------------------------------------
__global__ void ln_kernel(const float* __restrict__ x, const float* __restrict__ g,
                          const float* __restrict__ b, float* __restrict__ y, int n)
{
    int row = blockIdx.x * blockDim.y + threadIdx.y;
    if (row >= n) return;
    int lane = threadIdx.x;
    float4 v = reinterpret_cast<const float4*>(x + (size_t)row * 128)[lane];
    float s = v.x + v.y + v.z + v.w;
#pragma unroll
    for (int o = 16; o > 0; o >>= 1) s += __shfl_xor_sync(0xffffffffu, s, o);
    float mean = s * 0.0078125f;
    float dx = v.x - mean, dy = v.y - mean, dz = v.z - mean, dw = v.w - mean;
    float ss = dx * dx + dy * dy + dz * dz + dw * dw;
#pragma unroll
    for (int o = 16; o > 0; o >>= 1) ss += __shfl_xor_sync(0xffffffffu, ss, o);
    float inv = rsqrtf(ss * 0.0078125f + 1e-5f);
    float4 gg = reinterpret_cast<const float4*>(g)[lane];
    float4 bb = reinterpret_cast<const float4*>(b)[lane];
    float4 o4;
    o4.x = dx * inv * gg.x + bb.x;
    o4.y = dy * inv * gg.y + bb.y;
    o4.z = dz * inv * gg.z + bb.z;
    o4.w = dw * inv * gg.w + bb.w;
    reinterpret_cast<float4*>(y + (size_t)row * 128)[lane] = o4;
}

// ---------------------------------------------------------------------------
// Tiled SGEMM: C[M,N] = A[M,K] @ B[K,N] + bias (+ epilogue)
// BM=128, BN=64, BK=16, 256 threads, 8x4 per-thread tile.
// EPI: 0 = qkv (scale cols<128), 1 = +res (N=128), 2 = gelu, 3 = +res (N=128)
// ---------------------------------------------------------------------------
__device__ __forceinline__ float gelu_f(float x)
{
    float x3 = x * x * x;
    return 0.5f * x * (1.0f + tanhf(0.7978845608028654f * (x + 0.044715f * x3)));
}

template <int EPI>
__global__ void __launch_bounds__(256) gemm_k(
    const float* __restrict__ A, const float* __restrict__ B,
    const float* __restrict__ bias, const float* __restrict__ res,
    float* __restrict__ C, int M, int N, int K)
{
    __shared__ float As[16][132];   // transposed A tile, padded
    __shared__ float Bs[16][64];
    const int bm = blockIdx.x * 128;
    const int bn = blockIdx.y * 64;
    const int tid = threadIdx.x;
    const int tx = tid & 15;        // 16 col-groups of 4
    const int ty = tid >> 4;        // 16 row-groups of 8

    float acc[8][4];
#pragma unroll
    for (int i = 0; i < 8; i++)
#pragma unroll
        for (int j = 0; j < 4; j++) acc[i][j] = 0.0f;

    for (int k0 = 0; k0 < K; k0 += 16) {
        // --- load A tile (128x16) as float4, store transposed ---
#pragma unroll
        for (int i = 0; i < 2; i++) {
            int idx = tid + i * 256;       // 0..511
            int row = idx >> 2;            // 0..127
            int kq  = (idx & 3) << 2;      // 0,4,8,12
            float4 a = make_float4(0.f, 0.f, 0.f, 0.f);
            int gr = bm + row;
            if (gr < M)
                a = *reinterpret_cast<const float4*>(&A[(size_t)gr * K + k0 + kq]);
            As[kq + 0][row] = a.x;
            As[kq + 1][row] = a.y;
            As[kq + 2][row] = a.z;
            As[kq + 3][row] = a.w;
        }
        // --- load B tile (16x64) as float4 ---
        {
            int kr = tid >> 4;
            int c4 = (tid & 15) << 2;
            float4 bv = *reinterpret_cast<const float4*>(&B[(size_t)(k0 + kr) * N + bn + c4]);
            *reinterpret_cast<float4*>(&Bs[kr][c4]) = bv;
        }
        __syncthreads();

#pragma unroll
        for (int k = 0; k < 16; k++) {
            float4 a0 = *reinterpret_cast<const float4*>(&As[k][ty * 8]);
            float4 a1 = *reinterpret_cast<const float4*>(&As[k][ty * 8 + 4]);
            float4 bv = *reinterpret_cast<const float4*>(&Bs[k][tx * 4]);
            float am[8] = {a0.x, a0.y, a0.z, a0.w, a1.x, a1.y, a1.z, a1.w};
            float bw[4] = {bv.x, bv.y, bv.z, bv.w};
#pragma unroll
            for (int i = 0; i < 8; i++)
#pragma unroll
                for (int j = 0; j < 4; j++)
                    acc[i][j] = fmaf(am[i], bw[j], acc[i][j]);
        }
        __syncthreads();
    }

    // --- epilogue ---
    const int col = bn + tx * 4;
    float4 bb = *reinterpret_cast<const float4*>(&bias[col]);
#pragma unroll
    for (int i = 0; i < 8; i++) {
        int row = bm + ty * 8 + i;
        if (row >= M) continue;
        float v0 = acc[i][0] + bb.x;
        float v1 = acc[i][1] + bb.y;
        float v2 = acc[i][2] + bb.z;
        float v3 = acc[i][3] + bb.w;
        if (EPI == 0) {   // qkv: scale q columns (0..127)
            if (col < 128) { v0 *= SCALE_Q; v1 *= SCALE_Q; v2 *= SCALE_Q; v3 *= SCALE_Q; }
        }
        if (EPI == 1 || EPI == 3) {  // + residual (res has row-stride N)
            float4 rr = *reinterpret_cast<const float4*>(&res[(size_t)row * N + col]);
            v0 += rr.x; v1 += rr.y; v2 += rr.z; v3 += rr.w;
        }
        if (EPI == 2) {  // gelu (tanh approx, matches jax.nn.gelu default)
            v0 = gelu_f(v0); v1 = gelu_f(v1); v2 = gelu_f(v2); v3 = gelu_f(v3);
        }
        float4 o = make_float4(v0, v1, v2, v3);
        *reinterpret_cast<float4*>(&C[(size_t)row * N + col]) = o;
    }
}

// ---------------------------------------------------------------------------
// Edge scores: one warp per edge.
// scores[e][h] = sum_dh q[src[e], h, dh] * k[dst[e], h, dh] + edge_bias[e][h]
// (q already pre-scaled by SCALE in qkv epilogue)
// ---------------------------------------------------------------------------
__global__ void edge_scores_kernel(const int* __restrict__ src, const int* __restrict__ dst,
                                   const float* __restrict__ eb,
                                   const float* __restrict__ qkv,
                                   float* __restrict__ scores, int E)
{
    int warp = (blockIdx.x * blockDim.x + threadIdx.x) >> 5;
    if (warp >= E) return;
    int lane = threadIdx.x & 31;
    int s = src[warp];
    int d = dst[warp];
    float4 q = *reinterpret_cast<const float4*>(&qkv[(size_t)s * 384 + lane * 4]);
    float4 k = *reinterpret_cast<const float4*>(&qkv[(size_t)d * 384 + 128 + lane * 4]);
    float p = q.x * k.x + q.y * k.y + q.z * k.z + q.w * k.w;
    // reduce within groups of 4 lanes (16 floats = one head)
    p += __shfl_xor_sync(0xffffffffu, p, 1);
    p += __shfl_xor_sync(0xffffffffu, p, 2);
    if ((lane & 3) == 0) {
        int h = lane >> 2;
        scores[(size_t)warp * 8 + h] = p + eb[(size_t)warp * 8 + h];
    }
}

// ---------------------------------------------------------------------------
// Per-node aggregation: 128 threads per node (one per output dim d).
// softmax over the 16 incident edges per head, weighted sum of v[src[e]].
// ---------------------------------------------------------------------------
__global__ void aggregate_kernel(const int* __restrict__ inc_idx, const int* __restrict__ src,
                                 const float* __restrict__ scores,
                                 const float* __restrict__ qkv,
                                 float* __restrict__ attn)
{
    int n = blockIdx.x;
    int d = threadIdx.x;   // 0..127
    __shared__ int   e_sm[16];
    __shared__ int   vrow[16];
    __shared__ float s_sm[16][8];

    if (d < 16) {
        int e = inc_idx[(size_t)n * 16 + d];
        if (e < 0) e = 0;                 // jnp.clip(inc_idx, 0)
        e_sm[d] = e;
        vrow[d] = src[e];
    }
    __syncthreads();
    {
        int k = d >> 3, h = d & 7;        // 128 threads cover 16x8
        s_sm[k][h] = scores[(size_t)e_sm[k] * 8 + h];
    }
    __syncthreads();

    int h = d >> 4;
    float mx = -1e30f;
#pragma unroll
    for (int k = 0; k < 16; k++) mx = fmaxf(mx, s_sm[k][h]);
    float w[16];
    float se = 0.0f;
#pragma unroll
    for (int k = 0; k < 16; k++) { w[k] = __expf(s_sm[k][h] - mx); se += w[k]; }
    float inv = 1.0f / se;

    float accv = 0.0f;
#pragma unroll
    for (int k = 0; k < 16; k++)
        accv = fmaf(w[k] * inv, qkv[(size_t)vrow[k] * 384 + 256 + d], accv);

    attn[(size_t)n * 128 + d] = accv;
}

// ---------------------------------------------------------------------------
// Host launcher
// ---------------------------------------------------------------------------
extern "C" void kernel_launch(void* const* d_in, const int* in_sizes, int n_in,
                              void* d_out, int out_size)
{
    const float* triplet   = (const float*)d_in[0];
    const int*   src       = (const int*)  d_in[2];
    const int*   dst       = (const int*)  d_in[3];
    const float* edge_bias = (const float*)d_in[4];
    const int*   inc_idx   = (const int*)  d_in[6];
    const float* ln1_g     = (const float*)d_in[8];
    const float* ln1_b     = (const float*)d_in[9];
    const float* qkv_w     = (const float*)d_in[10];
    const float* qkv_b     = (const float*)d_in[11];
    const float* res_in_w  = (const float*)d_in[12];
    const float* res_in_b  = (const float*)d_in[13];
    const float* res_ln_g  = (const float*)d_in[14];
    const float* res_ln_b  = (const float*)d_in[15];
    const float* ffn_in_w  = (const float*)d_in[16];
    const float* ffn_in_b  = (const float*)d_in[17];
    const float* ffn_out_w = (const float*)d_in[18];
    const float* ffn_out_b = (const float*)d_in[19];

    const int N = in_sizes[0] / 128;
    const int E = in_sizes[2];

    float *xln, *qkv, *scores, *attn, *x2, *hid;
    cudaGetSymbolAddress((void**)&xln,    g_xln);
    cudaGetSymbolAddress((void**)&qkv,    g_qkv);
    cudaGetSymbolAddress((void**)&scores, g_scores);
    cudaGetSymbolAddress((void**)&attn,   g_attn);
    cudaGetSymbolAddress((void**)&x2,     g_x2);
    cudaGetSymbolAddress((void**)&hid,    g_hid);

    dim3 lnb(32, 8);
    int  lng = (N + 7) / 8;

    // 1) xln = LN(triplet_h)
    ln_kernel<<<lng, lnb>>>(triplet, ln1_g, ln1_b, xln, N);

    // 2) qkv = xln @ qkv_w + qkv_b  (q cols scaled)
    {
        dim3 grid((N + 127) / 128, 384 / 64);
        gemm_k<0><<<grid, 256>>>(xln, qkv_w, qkv_b, nullptr, qkv, N, 384, 128);
    }

    // 3) per-edge scores
    edge_scores_kernel<<<(E + 7) / 8, 256>>>(src, dst, edge_bias, qkv, scores, E);

    // 4) per-node softmax-weighted aggregation
    aggregate_kernel<<<N, 128>>>(inc_idx, src, scores, qkv, attn);

    // 5) x2 = triplet_h + attn @ res_in_w + res_in_b
    {
        dim3 grid((N + 127) / 128, 128 / 64);
        gemm_k<1><<<grid, 256>>>(attn, res_in_w, res_in_b, triplet, x2, N, 128, 128);
    }

    // 6) xln = LN(x2)
    ln_kernel<<<lng, lnb>>>(x2, res_ln_g, res_ln_b, xln, N);

    // 7) hid = gelu(xln @ ffn_in_w + ffn_in_b)
    {
        dim3 grid((N + 127) / 128, 512 / 64);
        gemm_k<2><<<grid, 256>>>(xln, ffn_in_w, ffn_in_b, nullptr, hid, N, 512, 128);
    }

    // 8) out = x2 + hid @ ffn_out_w + ffn_out_b
    {
        dim3 grid((N + 127) / 128, 128 / 64);
        gemm_k<3><<<grid, 256>>>(hid, ffn_out_w, ffn_out_b, x2, (float*)d_out, N, 128, 512);
    }
}

// round 2
// speedup vs baseline: 1.5506x; 1.5506x over previous
#include <cuda_runtime.h>
#include <stdint.h>
#include <math.h>

// Problem constants: N=50000, E=800000, K=16, D=128, H=8, DH=16
#define NMAX 50000
#define EMAX 800000
#define SCALE_Q 0.08838834764831845f   // 128^-0.5

// -------- scratch (device globals; no allocation in kernel_launch) --------
__device__ float g_xln[(size_t)NMAX * 128];
__device__ float g_qkv[(size_t)NMAX * 384];     // q|k|v
__device__ float g_scores[(size_t)EMAX * 8];
__device__ float g_attn[(size_t)NMAX * 128];
__device__ float g_x2[(size_t)NMAX * 128];
__device__ float g_hid[(size_t)NMAX * 512];

// ---------------------------------------------------------------------------
// LayerNorm: one row per warp
// ---------------------------------------------------------------------------
__global__ void ln_kernel(const float* __restrict__ x, const float* __restrict__ g,
                          const float* __restrict__ b, float* __restrict__ y, int n)
{
    int row = blockIdx.x * blockDim.y + threadIdx.y;
    if (row >= n) return;
    int lane = threadIdx.x;
    float4 v = reinterpret_cast<const float4*>(x + (size_t)row * 128)[lane];
    float s = v.x + v.y + v.z + v.w;
#pragma unroll
    for (int o = 16; o > 0; o >>= 1) s += __shfl_xor_sync(0xffffffffu, s, o);
    float mean = s * 0.0078125f;
    float dx = v.x - mean, dy = v.y - mean, dz = v.z - mean, dw = v.w - mean;
    float ss = dx * dx + dy * dy + dz * dz + dw * dw;
#pragma unroll
    for (int o = 16; o > 0; o >>= 1) ss += __shfl_xor_sync(0xffffffffu, ss, o);
    float inv = rsqrtf(ss * 0.0078125f + 1e-5f);
    float4 gg = reinterpret_cast<const float4*>(g)[lane];
    float4 bb = reinterpret_cast<const float4*>(b)[lane];
    float4 o4;
    o4.x = dx * inv * gg.x + bb.x;
    o4.y = dy * inv * gg.y + bb.y;
    o4.z = dz * inv * gg.z + bb.z;
    o4.w = dw * inv * gg.w + bb.w;
    reinterpret_cast<float4*>(y + (size_t)row * 128)[lane] = o4;
}

// ---------------------------------------------------------------------------
// TF32 tensor-core GEMM: C[M,N] = A[M,K] @ B[K,N] + bias (+ epilogue)
// BM=128, BN=64, BK=16; 8 warps (4m x 2n), warp tile 32x32 via m16n8k8 tf32.
// EPI: 0 = qkv (scale cols<128), 1/3 = +res (row-stride N), 2 = gelu
// ---------------------------------------------------------------------------
__device__ __forceinline__ uint32_t f2tf32(float f)
{
    uint32_t u;
    asm("cvt.rna.tf32.f32 %0, %1;" : "=r"(u) : "f"(f));
    return u;
}

__device__ __forceinline__ float gelu_f(float x)
{
    float x3 = x * x * x;
    return 0.5f * x * (1.0f + tanhf(0.7978845608028654f * (x + 0.044715f * x3)));
}

template <int EPI>
__global__ void __launch_bounds__(256) gemm_tc(
    const float* __restrict__ A, const float* __restrict__ B,
    const float* __restrict__ bias, const float* __restrict__ res,
    float* __restrict__ C, int M, int N, int K)
{
    __shared__ uint32_t As[128][20];   // [row][k], pad 20 -> conflict-free frags
    __shared__ uint32_t Bs[16][72];    // [k][col], pad 72 -> conflict-free frags

    const int bm = blockIdx.x * 128;
    const int bn = blockIdx.y * 64;
    const int tid  = threadIdx.x;
    const int lane = tid & 31;
    const int warp = tid >> 5;
    const int mw = warp & 3;           // 4 m-warps
    const int nw = warp >> 2;          // 2 n-warps
    const int g = lane >> 2;           // group id 0..7
    const int t = lane & 3;            // thread-in-group 0..3

    float acc[2][4][4];
#pragma unroll
    for (int mt = 0; mt < 2; mt++)
#pragma unroll
        for (int nt = 0; nt < 4; nt++)
#pragma unroll
            for (int c = 0; c < 4; c++) acc[mt][nt][c] = 0.0f;

    for (int k0 = 0; k0 < K; k0 += 16) {
        // --- A tile: 128x16 fp32 -> tf32 smem ---
#pragma unroll
        for (int i = 0; i < 2; i++) {
            int idx = tid + i * 256;      // 0..511
            int row = idx >> 2;           // 0..127
            int kq  = (idx & 3) << 2;     // 0,4,8,12
            int gr  = bm + row;
            float4 a = (gr < M) ? *reinterpret_cast<const float4*>(&A[(size_t)gr * K + k0 + kq])
                                : make_float4(0.f, 0.f, 0.f, 0.f);
            As[row][kq + 0] = f2tf32(a.x);
            As[row][kq + 1] = f2tf32(a.y);
            As[row][kq + 2] = f2tf32(a.z);
            As[row][kq + 3] = f2tf32(a.w);
        }
        // --- B tile: 16x64 fp32 -> tf32 smem ---
        {
            int kr = tid >> 4;            // 0..15
            int c4 = (tid & 15) << 2;     // 0..60
            float4 b = *reinterpret_cast<const float4*>(&B[(size_t)(k0 + kr) * N + bn + c4]);
            Bs[kr][c4 + 0] = f2tf32(b.x);
            Bs[kr][c4 + 1] = f2tf32(b.y);
            Bs[kr][c4 + 2] = f2tf32(b.z);
            Bs[kr][c4 + 3] = f2tf32(b.w);
        }
        __syncthreads();

#pragma unroll
        for (int kk = 0; kk < 16; kk += 8) {
            uint32_t af[2][4], bf[4][2];
#pragma unroll
            for (int mt = 0; mt < 2; mt++) {
                int r = mw * 32 + mt * 16 + g;
                af[mt][0] = As[r][kk + t];
                af[mt][1] = As[r + 8][kk + t];
                af[mt][2] = As[r][kk + t + 4];
                af[mt][3] = As[r + 8][kk + t + 4];
            }
#pragma unroll
            for (int nt = 0; nt < 4; nt++) {
                int c = nw * 32 + nt * 8 + g;
                bf[nt][0] = Bs[kk + t][c];
                bf[nt][1] = Bs[kk + t + 4][c];
            }
#pragma unroll
            for (int mt = 0; mt < 2; mt++)
#pragma unroll
                for (int nt = 0; nt < 4; nt++)
                    asm volatile(
                        "mma.sync.aligned.m16n8k8.row.col.f32.tf32.tf32.f32 "
                        "{%0,%1,%2,%3}, {%4,%5,%6,%7}, {%8,%9}, {%0,%1,%2,%3};"
                        : "+f"(acc[mt][nt][0]), "+f"(acc[mt][nt][1]),
                          "+f"(acc[mt][nt][2]), "+f"(acc[mt][nt][3])
                        : "r"(af[mt][0]), "r"(af[mt][1]), "r"(af[mt][2]), "r"(af[mt][3]),
                          "r"(bf[nt][0]), "r"(bf[nt][1]));
        }
        __syncthreads();
    }

    // --- epilogue ---
#pragma unroll
    for (int mt = 0; mt < 2; mt++) {
        int r0 = bm + mw * 32 + mt * 16 + g;
#pragma unroll
        for (int nt = 0; nt < 4; nt++) {
            int cb = bn + nw * 32 + nt * 8;
            int c0 = cb + 2 * t;
            float2 bb = *reinterpret_cast<const float2*>(&bias[c0]);
            float v0 = acc[mt][nt][0] + bb.x;
            float v1 = acc[mt][nt][1] + bb.y;
            float v2 = acc[mt][nt][2] + bb.x;
            float v3 = acc[mt][nt][3] + bb.y;
            if (EPI == 0 && cb < 128) {
                v0 *= SCALE_Q; v1 *= SCALE_Q; v2 *= SCALE_Q; v3 *= SCALE_Q;
            }
            if (EPI == 2) {
                v0 = gelu_f(v0); v1 = gelu_f(v1); v2 = gelu_f(v2); v3 = gelu_f(v3);
            }
            if (r0 < M) {
                if (EPI == 1 || EPI == 3) {
                    float2 rr = *reinterpret_cast<const float2*>(&res[(size_t)r0 * N + c0]);
                    v0 += rr.x; v1 += rr.y;
                }
                float2 o = make_float2(v0, v1);
                *reinterpret_cast<float2*>(&C[(size_t)r0 * N + c0]) = o;
            }
            if (r0 + 8 < M) {
                if (EPI == 1 || EPI == 3) {
                    float2 rr = *reinterpret_cast<const float2*>(&res[(size_t)(r0 + 8) * N + c0]);
                    v2 += rr.x; v3 += rr.y;
                }
                float2 o = make_float2(v2, v3);
                *reinterpret_cast<float2*>(&C[(size_t)(r0 + 8) * N + c0]) = o;
            }
        }
    }
}

// ---------------------------------------------------------------------------
// Edge scores: one warp per edge
// ---------------------------------------------------------------------------
__global__ void edge_scores_kernel(const int* __restrict__ src, const int* __restrict__ dst,
                                   const float* __restrict__ eb,
                                   const float* __restrict__ qkv,
                                   float* __restrict__ scores, int E)
{
    int warp = (blockIdx.x * blockDim.x + threadIdx.x) >> 5;
    if (warp >= E) return;
    int lane = threadIdx.x & 31;
    int s = src[warp];
    int d = dst[warp];
    float4 q = *reinterpret_cast<const float4*>(&qkv[(size_t)s * 384 + lane * 4]);
    float4 k = *reinterpret_cast<const float4*>(&qkv[(size_t)d * 384 + 128 + lane * 4]);
    float p = q.x * k.x + q.y * k.y + q.z * k.z + q.w * k.w;
    p += __shfl_xor_sync(0xffffffffu, p, 1);
    p += __shfl_xor_sync(0xffffffffu, p, 2);
    if ((lane & 3) == 0) {
        int h = lane >> 2;
        scores[(size_t)warp * 8 + h] = p + eb[(size_t)warp * 8 + h];
    }
}

// ---------------------------------------------------------------------------
// Per-node aggregation (softmax over 16 incident edges, per head)
// ---------------------------------------------------------------------------
__global__ void aggregate_kernel(const int* __restrict__ inc_idx, const int* __restrict__ src,
                                 const float* __restrict__ scores,
                                 const float* __restrict__ qkv,
                                 float* __restrict__ attn)
{
    int n = blockIdx.x;
    int d = threadIdx.x;   // 0..127
    __shared__ int   e_sm[16];
    __shared__ int   vrow[16];
    __shared__ float s_sm[16][8];

    if (d < 16) {
        int e = inc_idx[(size_t)n * 16 + d];
        if (e < 0) e = 0;
        e_sm[d] = e;
        vrow[d] = src[e];
    }
    __syncthreads();
    {
        int k = d >> 3, h = d & 7;
        s_sm[k][h] = scores[(size_t)e_sm[k] * 8 + h];
    }
    __syncthreads();

    int h = d >> 4;
    float mx = -1e30f;
#pragma unroll
    for (int k = 0; k < 16; k++) mx = fmaxf(mx, s_sm[k][h]);
    float w[16];
    float se = 0.0f;
#pragma unroll
    for (int k = 0; k < 16; k++) { w[k] = __expf(s_sm[k][h] - mx); se += w[k]; }
    float inv = 1.0f / se;

    float accv = 0.0f;
#pragma unroll
    for (int k = 0; k < 16; k++)
        accv = fmaf(w[k] * inv, qkv[(size_t)vrow[k] * 384 + 256 + d], accv);

    attn[(size_t)n * 128 + d] = accv;
}

// ---------------------------------------------------------------------------
// Host launcher
// ---------------------------------------------------------------------------
extern "C" void kernel_launch(void* const* d_in, const int* in_sizes, int n_in,
                              void* d_out, int out_size)
{
    const float* triplet   = (const float*)d_in[0];
    const int*   src       = (const int*)  d_in[2];
    const int*   dst       = (const int*)  d_in[3];
    const float* edge_bias = (const float*)d_in[4];
    const int*   inc_idx   = (const int*)  d_in[6];
    const float* ln1_g     = (const float*)d_in[8];
    const float* ln1_b     = (const float*)d_in[9];
    const float* qkv_w     = (const float*)d_in[10];
    const float* qkv_b     = (const float*)d_in[11];
    const float* res_in_w  = (const float*)d_in[12];
    const float* res_in_b  = (const float*)d_in[13];
    const float* res_ln_g  = (const float*)d_in[14];
    const float* res_ln_b  = (const float*)d_in[15];
    const float* ffn_in_w  = (const float*)d_in[16];
    const float* ffn_in_b  = (const float*)d_in[17];
    const float* ffn_out_w = (const float*)d_in[18];
    const float* ffn_out_b = (const float*)d_in[19];

    const int N = in_sizes[0] / 128;
    const int E = in_sizes[2];

    float *xln, *qkv, *scores, *attn, *x2, *hid;
    cudaGetSymbolAddress((void**)&xln,    g_xln);
    cudaGetSymbolAddress((void**)&qkv,    g_qkv);
    cudaGetSymbolAddress((void**)&scores, g_scores);
    cudaGetSymbolAddress((void**)&attn,   g_attn);
    cudaGetSymbolAddress((void**)&x2,     g_x2);
    cudaGetSymbolAddress((void**)&hid,    g_hid);

    dim3 lnb(32, 8);
    int  lng = (N + 7) / 8;
    int  mg  = (N + 127) / 128;

    // 1) xln = LN(triplet_h)
    ln_kernel<<<lng, lnb>>>(triplet, ln1_g, ln1_b, xln, N);

    // 2) qkv = xln @ qkv_w + qkv_b  (q cols scaled)
    gemm_tc<0><<<dim3(mg, 384 / 64), 256>>>(xln, qkv_w, qkv_b, nullptr, qkv, N, 384, 128);

    // 3) per-edge scores
    edge_scores_kernel<<<(E + 7) / 8, 256>>>(src, dst, edge_bias, qkv, scores, E);

    // 4) per-node aggregation
    aggregate_kernel<<<N, 128>>>(inc_idx, src, scores, qkv, attn);

    // 5) x2 = triplet_h + attn @ res_in_w + res_in_b
    gemm_tc<1><<<dim3(mg, 128 / 64), 256>>>(attn, res_in_w, res_in_b, triplet, x2, N, 128, 128);

    // 6) xln = LN(x2)
    ln_kernel<<<lng, lnb>>>(x2, res_ln_g, res_ln_b, xln, N);

    // 7) hid = gelu(xln @ ffn_in_w + ffn_in_b)
    gemm_tc<2><<<dim3(mg, 512 / 64), 256>>>(xln, ffn_in_w, ffn_in_b, nullptr, hid, N, 512, 128);

    // 8) out = x2 + hid @ ffn_out_w + ffn_out_b
    gemm_tc<3><<<dim3(mg, 128 / 64), 256>>>(hid, ffn_out_w, ffn_out_b, x2, (float*)d_out, N, 128, 512);
}

// round 3
// speedup vs baseline: 1.6926x; 1.0916x over previous
#include <cuda_runtime.h>
#include <cuda_bf16.h>
#include <stdint.h>
#include <math.h>

// Problem constants: N=50000, E=800000, K=16, D=128, H=8, DH=16
#define NMAX 50000
#define EMAX 800000
#define SCALE_Q 0.08838834764831845f   // 128^-0.5

// -------- scratch (device globals) --------
__device__ __nv_bfloat16 g_xln[(size_t)NMAX * 128];
__device__ __nv_bfloat16 g_qkv[(size_t)NMAX * 384];   // q|k|v, bf16
__device__ float         g_scores[(size_t)EMAX * 8];
__device__ __nv_bfloat16 g_attn[(size_t)NMAX * 128];
__device__ float         g_x2[(size_t)NMAX * 128];
__device__ __nv_bfloat16 g_hid[(size_t)NMAX * 512];

// ---------------------------------------------------------------------------
// LayerNorm: one row per warp; fp32 in, bf16 out
// ---------------------------------------------------------------------------
__global__ void ln_kernel(const float* __restrict__ x, const float* __restrict__ g,
                          const float* __restrict__ b, __nv_bfloat16* __restrict__ y, int n)
{
    int row = blockIdx.x * blockDim.y + threadIdx.y;
    if (row >= n) return;
    int lane = threadIdx.x;
    float4 v = reinterpret_cast<const float4*>(x + (size_t)row * 128)[lane];
    float s = v.x + v.y + v.z + v.w;
#pragma unroll
    for (int o = 16; o > 0; o >>= 1) s += __shfl_xor_sync(0xffffffffu, s, o);
    float mean = s * 0.0078125f;
    float dx = v.x - mean, dy = v.y - mean, dz = v.z - mean, dw = v.w - mean;
    float ss = dx * dx + dy * dy + dz * dz + dw * dw;
#pragma unroll
    for (int o = 16; o > 0; o >>= 1) ss += __shfl_xor_sync(0xffffffffu, ss, o);
    float inv = rsqrtf(ss * 0.0078125f + 1e-5f);
    float4 gg = reinterpret_cast<const float4*>(g)[lane];
    float4 bb = reinterpret_cast<const float4*>(b)[lane];
    __nv_bfloat162 o0 = __floats2bfloat162_rn(dx * inv * gg.x + bb.x, dy * inv * gg.y + bb.y);
    __nv_bfloat162 o1 = __floats2bfloat162_rn(dz * inv * gg.z + bb.z, dw * inv * gg.w + bb.w);
    uint2 pack;
    pack.x = *reinterpret_cast<uint32_t*>(&o0);
    pack.y = *reinterpret_cast<uint32_t*>(&o1);
    reinterpret_cast<uint2*>(y + (size_t)row * 128)[lane] = pack;
}

// ---------------------------------------------------------------------------
// BF16 tensor-core GEMM: C = A(bf16)[M,K] @ B(f32->bf16)[K,N] + bias
// BM=128, BN=64, BK=32; 8 warps (4m x 2n), warp tile 32x32 via m16n8k16.
// EPI: 0 = qkv->bf16 (scale cols<128), 1 = +res -> f32, 2 = gelu->bf16,
//      3 = +res -> f32
// ---------------------------------------------------------------------------
__device__ __forceinline__ float gelu_f(float x)
{
    float x3 = x * x * x;
    return 0.5f * x * (1.0f + tanhf(0.7978845608028654f * (x + 0.044715f * x3)));
}

template <int EPI>
__global__ void __launch_bounds__(256) gemm_bf16(
    const __nv_bfloat16* __restrict__ A, const float* __restrict__ B,
    const float* __restrict__ bias, const float* __restrict__ res,
    void* __restrict__ Cv, int M, int N, int K)
{
    __shared__ __nv_bfloat16 As[128][40];  // [row][k], stride 40 (80B, 16B aligned)
    __shared__ __nv_bfloat16 Bs[64][40];   // [n][k] (transposed), stride 40

    const int bm = blockIdx.x * 128;
    const int bn = blockIdx.y * 64;
    const int tid  = threadIdx.x;
    const int lane = tid & 31;
    const int warp = tid >> 5;
    const int mw = warp & 3;
    const int nw = warp >> 2;
    const int g = lane >> 2;
    const int t = lane & 3;

    float acc[2][4][4];
#pragma unroll
    for (int mt = 0; mt < 2; mt++)
#pragma unroll
        for (int nt = 0; nt < 4; nt++)
#pragma unroll
            for (int c = 0; c < 4; c++) acc[mt][nt][c] = 0.0f;

    for (int k0 = 0; k0 < K; k0 += 32) {
        // --- A tile: 128x32 bf16 (uint4 = 8 bf16 per load) ---
#pragma unroll
        for (int i = 0; i < 2; i++) {
            int idx = tid + i * 256;          // 0..511
            int row = idx >> 2;               // 0..127
            int kc  = (idx & 3) << 3;         // 0,8,16,24
            int gr  = bm + row;
            uint4 a = make_uint4(0u, 0u, 0u, 0u);
            if (gr < M)
                a = *reinterpret_cast<const uint4*>(&A[(size_t)gr * K + k0 + kc]);
            *reinterpret_cast<uint4*>(&As[row][kc]) = a;
        }
        // --- B tile: 32x64 f32 -> bf16 transposed into Bs[n][k] ---
#pragma unroll
        for (int i = 0; i < 2; i++) {
            int idx = tid + i * 256;          // 0..511 float4 units
            int kr = idx >> 4;                // 0..31
            int c4 = (idx & 15) << 2;         // 0..60
            float4 b = *reinterpret_cast<const float4*>(&B[(size_t)(k0 + kr) * N + bn + c4]);
            Bs[c4 + 0][kr] = __float2bfloat16_rn(b.x);
            Bs[c4 + 1][kr] = __float2bfloat16_rn(b.y);
            Bs[c4 + 2][kr] = __float2bfloat16_rn(b.z);
            Bs[c4 + 3][kr] = __float2bfloat16_rn(b.w);
        }
        __syncthreads();

#pragma unroll
        for (int kk = 0; kk < 32; kk += 16) {
            uint32_t af[2][4], bfr[4][2];
#pragma unroll
            for (int mt = 0; mt < 2; mt++) {
                int r = mw * 32 + mt * 16 + g;
                af[mt][0] = *reinterpret_cast<const uint32_t*>(&As[r][kk + 2 * t]);
                af[mt][1] = *reinterpret_cast<const uint32_t*>(&As[r + 8][kk + 2 * t]);
                af[mt][2] = *reinterpret_cast<const uint32_t*>(&As[r][kk + 2 * t + 8]);
                af[mt][3] = *reinterpret_cast<const uint32_t*>(&As[r + 8][kk + 2 * t + 8]);
            }
#pragma unroll
            for (int nt = 0; nt < 4; nt++) {
                int c = nw * 32 + nt * 8 + g;
                bfr[nt][0] = *reinterpret_cast<const uint32_t*>(&Bs[c][kk + 2 * t]);
                bfr[nt][1] = *reinterpret_cast<const uint32_t*>(&Bs[c][kk + 2 * t + 8]);
            }
#pragma unroll
            for (int mt = 0; mt < 2; mt++)
#pragma unroll
                for (int nt = 0; nt < 4; nt++)
                    asm volatile(
                        "mma.sync.aligned.m16n8k16.row.col.f32.bf16.bf16.f32 "
                        "{%0,%1,%2,%3}, {%4,%5,%6,%7}, {%8,%9}, {%0,%1,%2,%3};"
                        : "+f"(acc[mt][nt][0]), "+f"(acc[mt][nt][1]),
                          "+f"(acc[mt][nt][2]), "+f"(acc[mt][nt][3])
                        : "r"(af[mt][0]), "r"(af[mt][1]), "r"(af[mt][2]), "r"(af[mt][3]),
                          "r"(bfr[nt][0]), "r"(bfr[nt][1]));
        }
        __syncthreads();
    }

    // --- epilogue ---
    float* Cf = (float*)Cv;
    __nv_bfloat16* Cb = (__nv_bfloat16*)Cv;
#pragma unroll
    for (int mt = 0; mt < 2; mt++) {
        int r0 = bm + mw * 32 + mt * 16 + g;
#pragma unroll
        for (int nt = 0; nt < 4; nt++) {
            int cb = bn + nw * 32 + nt * 8;
            int c0 = cb + 2 * t;
            float2 bb = *reinterpret_cast<const float2*>(&bias[c0]);
            float v0 = acc[mt][nt][0] + bb.x;
            float v1 = acc[mt][nt][1] + bb.y;
            float v2 = acc[mt][nt][2] + bb.x;
            float v3 = acc[mt][nt][3] + bb.y;
            if (EPI == 0 && cb < 128) {
                v0 *= SCALE_Q; v1 *= SCALE_Q; v2 *= SCALE_Q; v3 *= SCALE_Q;
            }
            if (EPI == 2) {
                v0 = gelu_f(v0); v1 = gelu_f(v1); v2 = gelu_f(v2); v3 = gelu_f(v3);
            }
            if (r0 < M) {
                if (EPI == 1 || EPI == 3) {
                    float2 rr = *reinterpret_cast<const float2*>(&res[(size_t)r0 * N + c0]);
                    *reinterpret_cast<float2*>(&Cf[(size_t)r0 * N + c0]) =
                        make_float2(v0 + rr.x, v1 + rr.y);
                } else {
                    __nv_bfloat162 o = __floats2bfloat162_rn(v0, v1);
                    *reinterpret_cast<__nv_bfloat162*>(&Cb[(size_t)r0 * N + c0]) = o;
                }
            }
            if (r0 + 8 < M) {
                if (EPI == 1 || EPI == 3) {
                    float2 rr = *reinterpret_cast<const float2*>(&res[(size_t)(r0 + 8) * N + c0]);
                    *reinterpret_cast<float2*>(&Cf[(size_t)(r0 + 8) * N + c0]) =
                        make_float2(v2 + rr.x, v3 + rr.y);
                } else {
                    __nv_bfloat162 o = __floats2bfloat162_rn(v2, v3);
                    *reinterpret_cast<__nv_bfloat162*>(&Cb[(size_t)(r0 + 8) * N + c0]) = o;
                }
            }
        }
    }
}

// ---------------------------------------------------------------------------
// Edge scores: one warp per edge, bf16 q/k gathers
// ---------------------------------------------------------------------------
__global__ void edge_scores_kernel(const int* __restrict__ src, const int* __restrict__ dst,
                                   const float* __restrict__ eb,
                                   const __nv_bfloat16* __restrict__ qkv,
                                   float* __restrict__ scores, int E)
{
    int warp = (blockIdx.x * blockDim.x + threadIdx.x) >> 5;
    if (warp >= E) return;
    int lane = threadIdx.x & 31;
    int s = src[warp];
    int d = dst[warp];
    uint2 qu = *reinterpret_cast<const uint2*>(&qkv[(size_t)s * 384 + lane * 4]);
    uint2 ku = *reinterpret_cast<const uint2*>(&qkv[(size_t)d * 384 + 128 + lane * 4]);
    float2 q0 = __bfloat1622float2(*reinterpret_cast<__nv_bfloat162*>(&qu.x));
    float2 q1 = __bfloat1622float2(*reinterpret_cast<__nv_bfloat162*>(&qu.y));
    float2 k0 = __bfloat1622float2(*reinterpret_cast<__nv_bfloat162*>(&ku.x));
    float2 k1 = __bfloat1622float2(*reinterpret_cast<__nv_bfloat162*>(&ku.y));
    float p = q0.x * k0.x + q0.y * k0.y + q1.x * k1.x + q1.y * k1.y;
    p += __shfl_xor_sync(0xffffffffu, p, 1);
    p += __shfl_xor_sync(0xffffffffu, p, 2);
    if ((lane & 3) == 0) {
        int h = lane >> 2;
        scores[(size_t)warp * 8 + h] = p + eb[(size_t)warp * 8 + h];
    }
}

// ---------------------------------------------------------------------------
// Per-node aggregation (softmax over 16 incident edges per head), bf16 v
// ---------------------------------------------------------------------------
__global__ void aggregate_kernel(const int* __restrict__ inc_idx, const int* __restrict__ src,
                                 const float* __restrict__ scores,
                                 const __nv_bfloat16* __restrict__ qkv,
                                 __nv_bfloat16* __restrict__ attn)
{
    int n = blockIdx.x;
    int d = threadIdx.x;   // 0..127
    __shared__ int   e_sm[16];
    __shared__ const __nv_bfloat16* vptr[16];
    __shared__ float s_sm[16][8];

    if (d < 16) {
        int e = inc_idx[(size_t)n * 16 + d];
        if (e < 0) e = 0;
        e_sm[d] = e;
        vptr[d] = qkv + (size_t)src[e] * 384 + 256;
    }
    __syncthreads();
    {
        int k = d >> 3, h = d & 7;
        s_sm[k][h] = scores[(size_t)e_sm[k] * 8 + h];
    }
    __syncthreads();

    int h = d >> 4;
    float mx = -1e30f;
#pragma unroll
    for (int k = 0; k < 16; k++) mx = fmaxf(mx, s_sm[k][h]);
    float w[16];
    float se = 0.0f;
#pragma unroll
    for (int k = 0; k < 16; k++) { w[k] = __expf(s_sm[k][h] - mx); se += w[k]; }
    float inv = 1.0f / se;

    float accv = 0.0f;
#pragma unroll
    for (int k = 0; k < 16; k++)
        accv = fmaf(w[k] * inv, __bfloat162float(vptr[k][d]), accv);

    attn[(size_t)n * 128 + d] = __float2bfloat16_rn(accv);
}

// ---------------------------------------------------------------------------
// Host launcher
// ---------------------------------------------------------------------------
extern "C" void kernel_launch(void* const* d_in, const int* in_sizes, int n_in,
                              void* d_out, int out_size)
{
    const float* triplet   = (const float*)d_in[0];
    const int*   src       = (const int*)  d_in[2];
    const int*   dst       = (const int*)  d_in[3];
    const float* edge_bias = (const float*)d_in[4];
    const int*   inc_idx   = (const int*)  d_in[6];
    const float* ln1_g     = (const float*)d_in[8];
    const float* ln1_b     = (const float*)d_in[9];
    const float* qkv_w     = (const float*)d_in[10];
    const float* qkv_b     = (const float*)d_in[11];
    const float* res_in_w  = (const float*)d_in[12];
    const float* res_in_b  = (const float*)d_in[13];
    const float* res_ln_g  = (const float*)d_in[14];
    const float* res_ln_b  = (const float*)d_in[15];
    const float* ffn_in_w  = (const float*)d_in[16];
    const float* ffn_in_b  = (const float*)d_in[17];
    const float* ffn_out_w = (const float*)d_in[18];
    const float* ffn_out_b = (const float*)d_in[19];

    const int N = in_sizes[0] / 128;
    const int E = in_sizes[2];

    __nv_bfloat16 *xln, *qkv, *attn, *hid;
    float *scores, *x2;
    cudaGetSymbolAddress((void**)&xln,    g_xln);
    cudaGetSymbolAddress((void**)&qkv,    g_qkv);
    cudaGetSymbolAddress((void**)&scores, g_scores);
    cudaGetSymbolAddress((void**)&attn,   g_attn);
    cudaGetSymbolAddress((void**)&x2,     g_x2);
    cudaGetSymbolAddress((void**)&hid,    g_hid);

    dim3 lnb(32, 8);
    int  lng = (N + 7) / 8;
    int  mg  = (N + 127) / 128;

    // 1) xln = LN(triplet_h)   (bf16 out)
    ln_kernel<<<lng, lnb>>>(triplet, ln1_g, ln1_b, xln, N);

    // 2) qkv = xln @ qkv_w + qkv_b  (bf16 out, q cols scaled)
    gemm_bf16<0><<<dim3(mg, 384 / 64), 256>>>(xln, qkv_w, qkv_b, nullptr, qkv, N, 384, 128);

    // 3) per-edge scores
    edge_scores_kernel<<<(E + 7) / 8, 256>>>(src, dst, edge_bias, qkv, scores, E);

    // 4) per-node aggregation (bf16 out)
    aggregate_kernel<<<N, 128>>>(inc_idx, src, scores, qkv, attn);

    // 5) x2 = triplet_h + attn @ res_in_w + res_in_b   (f32 out)
    gemm_bf16<1><<<dim3(mg, 128 / 64), 256>>>(attn, res_in_w, res_in_b, triplet, x2, N, 128, 128);

    // 6) xln = LN(x2)   (bf16 out)
    ln_kernel<<<lng, lnb>>>(x2, res_ln_g, res_ln_b, xln, N);

    // 7) hid = gelu(xln @ ffn_in_w + ffn_in_b)   (bf16 out)
    gemm_bf16<2><<<dim3(mg, 512 / 64), 256>>>(xln, ffn_in_w, ffn_in_b, nullptr, hid, N, 512, 128);

    // 8) out = x2 + hid @ ffn_out_w + ffn_out_b   (f32 out)
    gemm_bf16<3><<<dim3(mg, 128 / 64), 256>>>(hid, ffn_out_w, ffn_out_b, x2, (float*)d_out, N, 128, 512);
}

// round 5
// speedup vs baseline: 3.5997x; 2.1268x over previous
#include <cuda_runtime.h>
#include <cuda_bf16.h>
#include <stdint.h>
#include <math.h>

// Problem constants: N=50000, E=800000, K=16, D=128, H=8, DH=16
#define NMAX 50000
#define EMAX 800000
#define NTILE 391                     // ceil(50000/128)
#define NPAD  (NTILE * 128)           // 50048 padded rows
#define SCALE_Q 0.08838834764831845f  // 128^-0.5

// -------- scratch (device globals; zero-initialized) --------
__device__ __nv_bfloat16 g_xln [(size_t)NPAD * 128];
__device__ __nv_bfloat16 g_attn[(size_t)NPAD * 128];
__device__ __nv_bfloat16 g_hid [(size_t)NPAD * 512];
__device__ __nv_bfloat16 g_qkv [(size_t)NPAD * 384];
__device__ float         g_scores[(size_t)EMAX * 8];
__device__ float         g_x2[(size_t)NMAX * 128];
// bf16 W^T, [N][K] K-major
__device__ __nv_bfloat16 g_wq[384 * 128];
__device__ __nv_bfloat16 g_wr[128 * 128];
__device__ __nv_bfloat16 g_w1[512 * 128];
__device__ __nv_bfloat16 g_w2[128 * 512];

// -------- helpers --------
__device__ __forceinline__ uint32_t smem_u32(const void* p)
{
    uint32_t a;
    asm("{ .reg .u64 t; cvta.to.shared.u64 t, %1; cvt.u32.u64 %0, t; }" : "=r"(a) : "l"(p));
    return a;
}
__device__ __forceinline__ void cp16(uint32_t dst, const void* src)
{
    asm volatile("cp.async.cg.shared.global [%0], [%1], 16;" :: "r"(dst), "l"(src));
}
__device__ __forceinline__ void ldsm_x4(uint32_t* r, uint32_t addr)
{
    asm volatile("ldmatrix.sync.aligned.m8n8.x4.shared.b16 {%0,%1,%2,%3}, [%4];"
                 : "=r"(r[0]), "=r"(r[1]), "=r"(r[2]), "=r"(r[3]) : "r"(addr));
}
__device__ __forceinline__ void mma16816(float* acc, const uint32_t* a,
                                         uint32_t b0, uint32_t b1)
{
    asm volatile(
        "mma.sync.aligned.m16n8k16.row.col.f32.bf16.bf16.f32 "
        "{%0,%1,%2,%3}, {%4,%5,%6,%7}, {%8,%9}, {%0,%1,%2,%3};"
        : "+f"(acc[0]), "+f"(acc[1]), "+f"(acc[2]), "+f"(acc[3])
        : "r"(a[0]), "r"(a[1]), "r"(a[2]), "r"(a[3]), "r"(b0), "r"(b1));
}
__device__ __forceinline__ int swzo(int c2, int sw)
{
    return (c2 & ~127) | ((c2 & 127) ^ sw);
}
__device__ __forceinline__ float gelu_f(float x)
{
    float x3 = x * x * x;
    return 0.5f * x * (1.0f + tanhf(0.7978845608028654f * (x + 0.044715f * x3)));
}

// ---------------------------------------------------------------------------
// Weight prep: f32 W[K,N] -> bf16 W^T[n][k] (write-coalesced)
// ---------------------------------------------------------------------------
__global__ void prep_weights(const float* __restrict__ wq, const float* __restrict__ wr,
                             const float* __restrict__ w1, const float* __restrict__ w2,
                             __nv_bfloat16* bq, __nv_bfloat16* br,
                             __nv_bfloat16* b1, __nv_bfloat16* b2)
{
    int i = blockIdx.x * 256 + threadIdx.x;          // 0..196607
    if (i < 49152) {                                 // qkv_w: K=128, N=384
        int n = i >> 7, k = i & 127;
        bq[i] = __float2bfloat16_rn(wq[k * 384 + n]);
    } else if (i < 49152 + 16384) {                  // res_in_w 128x128
        int j = i - 49152;
        int n = j >> 7, k = j & 127;
        br[j] = __float2bfloat16_rn(wr[k * 128 + n]);
    } else if (i < 49152 + 16384 + 65536) {          // ffn_in_w: K=128, N=512
        int j = i - 49152 - 16384;
        int n = j >> 7, k = j & 127;
        b1[j] = __float2bfloat16_rn(w1[k * 512 + n]);
    } else {                                         // ffn_out_w: K=512, N=128
        int j = i - 49152 - 16384 - 65536;
        int n = j >> 9, k = j & 511;
        b2[j] = __float2bfloat16_rn(w2[k * 128 + n]);
    }
}

// ---------------------------------------------------------------------------
// LayerNorm: one row per warp; fp32 in, bf16 out
// ---------------------------------------------------------------------------
__global__ void ln_kernel(const float* __restrict__ x, const float* __restrict__ g,
                          const float* __restrict__ b, __nv_bfloat16* __restrict__ y, int n)
{
    int row = blockIdx.x * blockDim.y + threadIdx.y;
    if (row >= n) return;
    int lane = threadIdx.x;
    float4 v = reinterpret_cast<const float4*>(x + (size_t)row * 128)[lane];
    float s = v.x + v.y + v.z + v.w;
#pragma unroll
    for (int o = 16; o > 0; o >>= 1) s += __shfl_xor_sync(0xffffffffu, s, o);
    float mean = s * 0.0078125f;
    float dx = v.x - mean, dy = v.y - mean, dz = v.z - mean, dw = v.w - mean;
    float ss = dx * dx + dy * dy + dz * dz + dw * dw;
#pragma unroll
    for (int o = 16; o > 0; o >>= 1) ss += __shfl_xor_sync(0xffffffffu, ss, o);
    float inv = rsqrtf(ss * 0.0078125f + 1e-5f);
    float4 gg = reinterpret_cast<const float4*>(g)[lane];
    float4 bb = reinterpret_cast<const float4*>(b)[lane];
    __nv_bfloat162 o0 = __floats2bfloat162_rn(dx * inv * gg.x + bb.x, dy * inv * gg.y + bb.y);
    __nv_bfloat162 o1 = __floats2bfloat162_rn(dz * inv * gg.z + bb.z, dw * inv * gg.w + bb.w);
    uint2 pack;
    pack.x = *reinterpret_cast<uint32_t*>(&o0);
    pack.y = *reinterpret_cast<uint32_t*>(&o1);
    reinterpret_cast<uint2*>(y + (size_t)row * 128)[lane] = pack;
}

// ---------------------------------------------------------------------------
// bf16 mma.sync GEMM with ldmatrix frags + cp.async tiles.
// C[M, 128*gy] tile = A[M,KTOT] @ WT[128*gy][KTOT]^T + bias
// BM=128, BN=128, 256 threads (8 warps: 4m x 2n), warp tile 32x64.
// EPI: 0 qkv->bf16 (scale gy==0), 1 +res->f32, 2 gelu->bf16, 3 +res->f32
// ---------------------------------------------------------------------------
template <int EPI, int KTOT, int CK>
__global__ void __launch_bounds__(256) gemm_mma(
    const __nv_bfloat16* __restrict__ A, const __nv_bfloat16* __restrict__ WT,
    const float* __restrict__ bias, const float* __restrict__ res,
    void* __restrict__ Cv, int M)
{
    constexpr int CHUNKS = KTOT / CK;
    constexpr int STAGES = (CHUNKS > 1) ? 2 : 1;
    constexpr int ROWB   = CK * 2;            // bytes per smem row
    constexpr int HALF   = 128 * ROWB;        // A-part bytes per stage
    constexpr int STAGE  = 2 * HALF;
    constexpr int CPR    = CK / 8;            // 16B chunks per row

    extern __shared__ char smraw[];
    const uint32_t sbase = smem_u32(smraw);

    const int tid  = threadIdx.x;
    const int lane = tid & 31;
    const int warp = tid >> 5;
    const int mw = warp & 3;                  // 4 m-warps
    const int nw = warp >> 2;                 // 2 n-warps

    const char* Ab  = (const char*)(A  + (size_t)blockIdx.x * 128 * KTOT);
    const char* WTb = (const char*)(WT + (size_t)blockIdx.y * 128 * KTOT);

    float acc[2][8][4];
#pragma unroll
    for (int mt = 0; mt < 2; mt++)
#pragma unroll
        for (int nt = 0; nt < 8; nt++)
#pragma unroll
            for (int c = 0; c < 4; c++) acc[mt][nt][c] = 0.0f;

    // ---- ldmatrix per-lane address components ----
    int aoff[2], asw[2];
#pragma unroll
    for (int mt = 0; mt < 2; mt++) {
        int r = mw * 32 + mt * 16 + (lane & 7) + ((lane >> 3) & 1) * 8;
        aoff[mt] = r * ROWB;
        asw[mt]  = (r & 7) << 4;
    }
    const int akh = ((lane >> 4) & 1) * 16;
    int boff[4], bsw[4];
#pragma unroll
    for (int p = 0; p < 4; p++) {
        int r = nw * 64 + p * 16 + ((lane >> 4) & 1) * 8 + (lane & 7);
        boff[p] = r * ROWB;
        bsw[p]  = (r & 7) << 4;
    }
    const int bkh = ((lane >> 3) & 1) * 16;

    // ---- tile loader: chunk c -> stage s ----
    auto load_chunk = [&](int s, int c) {
        uint32_t dA = sbase + s * STAGE;
        uint32_t dB = dA + HALF;
#pragma unroll
        for (int i = tid; i < 16 * CK; i += 256) {
            int row = i / CPR, cc = i % CPR;
            int so = swzo(cc * 16, (row & 7) << 4);
            cp16(dA + row * ROWB + so,
                 Ab + (size_t)row * (KTOT * 2) + c * (CK * 2) + cc * 16);
            cp16(dB + row * ROWB + so,
                 WTb + (size_t)row * (KTOT * 2) + c * (CK * 2) + cc * 16);
        }
        asm volatile("cp.async.commit_group;" ::: "memory");
    };

    auto compute = [&](int s) {
        uint32_t bA = sbase + s * STAGE;
        uint32_t bB = bA + HALF;
#pragma unroll
        for (int kk = 0; kk < CK; kk += 16) {
            uint32_t a[2][4], bb[4][4];
#pragma unroll
            for (int mt = 0; mt < 2; mt++) {
                int c2 = kk * 2 + akh;
                ldsm_x4(a[mt], bA + aoff[mt] + swzo(c2, asw[mt]));
            }
#pragma unroll
            for (int p = 0; p < 4; p++) {
                int c2 = kk * 2 + bkh;
                ldsm_x4(bb[p], bB + boff[p] + swzo(c2, bsw[p]));
            }
#pragma unroll
            for (int mt = 0; mt < 2; mt++)
#pragma unroll
                for (int nt = 0; nt < 8; nt++) {
                    int p = nt >> 1, hi = (nt & 1) * 2;
                    mma16816(acc[mt][nt], a[mt], bb[p][hi], bb[p][hi + 1]);
                }
        }
    };

    load_chunk(0, 0);
    if (CHUNKS > 1) load_chunk(1, 1);

#pragma unroll 1
    for (int c = 0; c < CHUNKS; c++) {
        if (CHUNKS > 1 && c < CHUNKS - 1)
            asm volatile("cp.async.wait_group 1;" ::: "memory");
        else
            asm volatile("cp.async.wait_group 0;" ::: "memory");
        __syncthreads();
        compute(c & (STAGES - 1));
        if (c + 2 < CHUNKS + 1 && CHUNKS > 1 && c + 2 <= CHUNKS - 1 + 1) {}
        if (CHUNKS > 1 && c + 2 <= CHUNKS - 1) {
            __syncthreads();
            load_chunk(c & 1, c + 2);
        } else if (CHUNKS > 1 && c < CHUNKS - 1) {
            __syncthreads();
        }
    }

    // ---- epilogue ----
    const int g4 = lane >> 2, t4 = lane & 3;
#pragma unroll
    for (int mt = 0; mt < 2; mt++) {
        int row = blockIdx.x * 128 + mw * 32 + mt * 16 + g4;
#pragma unroll
        for (int nt = 0; nt < 8; nt++) {
            int cl = nw * 64 + nt * 8 + 2 * t4;       // col within 128-tile
            float* ac = acc[mt][nt];
            if (EPI == 0) {
                int cg = blockIdx.y * 128 + cl;
                float b0 = bias[cg], b1 = bias[cg + 1];
                float v0 = ac[0] + b0, v1 = ac[1] + b1;
                float v2 = ac[2] + b0, v3 = ac[3] + b1;
                if (blockIdx.y == 0) { v0 *= SCALE_Q; v1 *= SCALE_Q; v2 *= SCALE_Q; v3 *= SCALE_Q; }
                __nv_bfloat16* out = (__nv_bfloat16*)Cv;
                *reinterpret_cast<__nv_bfloat162*>(out + (size_t)row * 384 + cg) =
                    __floats2bfloat162_rn(v0, v1);
                *reinterpret_cast<__nv_bfloat162*>(out + (size_t)(row + 8) * 384 + cg) =
                    __floats2bfloat162_rn(v2, v3);
            } else if (EPI == 2) {
                int cg = blockIdx.y * 128 + cl;
                float b0 = bias[cg], b1 = bias[cg + 1];
                __nv_bfloat16* out = (__nv_bfloat16*)Cv;
                *reinterpret_cast<__nv_bfloat162*>(out + (size_t)row * 512 + cg) =
                    __floats2bfloat162_rn(gelu_f(ac[0] + b0), gelu_f(ac[1] + b1));
                *reinterpret_cast<__nv_bfloat162*>(out + (size_t)(row + 8) * 512 + cg) =
                    __floats2bfloat162_rn(gelu_f(ac[2] + b0), gelu_f(ac[3] + b1));
            } else {  // EPI 1/3: f32 out + residual, N=128
                float b0 = bias[cl], b1 = bias[cl + 1];
                float* out = (float*)Cv;
                if (row < M) {
                    float2 rr = *reinterpret_cast<const float2*>(res + (size_t)row * 128 + cl);
                    *reinterpret_cast<float2*>(out + (size_t)row * 128 + cl) =
                        make_float2(ac[0] + b0 + rr.x, ac[1] + b1 + rr.y);
                }
                if (row + 8 < M) {
                    float2 rr = *reinterpret_cast<const float2*>(res + (size_t)(row + 8) * 128 + cl);
                    *reinterpret_cast<float2*>(out + (size_t)(row + 8) * 128 + cl) =
                        make_float2(ac[2] + b0 + rr.x, ac[3] + b1 + rr.y);
                }
            }
        }
    }
}

// ---------------------------------------------------------------------------
// Edge scores: one head per lane (8 lanes per edge)
// ---------------------------------------------------------------------------
__global__ void edge_scores_kernel(const int* __restrict__ src, const int* __restrict__ dst,
                                   const float* __restrict__ eb,
                                   const __nv_bfloat16* __restrict__ qkv,
                                   float* __restrict__ scores, int E)
{
    int gt = blockIdx.x * blockDim.x + threadIdx.x;
    int e = gt >> 3;
    if (e >= E) return;
    int h = gt & 7;
    int s = src[e], d = dst[e];
    const uint4* qp = reinterpret_cast<const uint4*>(qkv + (size_t)s * 384 + h * 16);
    const uint4* kp = reinterpret_cast<const uint4*>(qkv + (size_t)d * 384 + 128 + h * 16);
    uint4 q0 = qp[0], q1 = qp[1];
    uint4 k0 = kp[0], k1 = kp[1];
    float acc = 0.0f;
#define DOT2(ua, ub) { \
    float2 fa = __bfloat1622float2(*reinterpret_cast<__nv_bfloat162*>(&(ua))); \
    float2 fb = __bfloat1622float2(*reinterpret_cast<__nv_bfloat162*>(&(ub))); \
    acc = fmaf(fa.x, fb.x, acc); acc = fmaf(fa.y, fb.y, acc); }
    DOT2(q0.x, k0.x) DOT2(q0.y, k0.y) DOT2(q0.z, k0.z) DOT2(q0.w, k0.w)
    DOT2(q1.x, k1.x) DOT2(q1.y, k1.y) DOT2(q1.z, k1.z) DOT2(q1.w, k1.w)
#undef DOT2
    scores[(size_t)e * 8 + h] = acc + eb[(size_t)e * 8 + h];
}

// ---------------------------------------------------------------------------
// Aggregation: 2 nodes per 128-thread block; softmax once per (node, head)
// ---------------------------------------------------------------------------
__global__ void aggregate_kernel(const int* __restrict__ inc_idx, const int* __restrict__ src,
                                 const float* __restrict__ scores,
                                 const __nv_bfloat16* __restrict__ qkv,
                                 __nv_bfloat16* __restrict__ attn, int N)
{
    int tid = threadIdx.x;
    int base_n = blockIdx.x * 2;
    __shared__ int   e_sm[2][16];
    __shared__ int   vrow[2][16];
    __shared__ float s_sm[2][16][8];
    __shared__ float w_sm[2][16][8];

    if (tid < 32) {
        int which = tid >> 4, k = tid & 15;
        int n = base_n + which;
        int e = 0;
        if (n < N) {
            e = inc_idx[(size_t)n * 16 + k];
            if (e < 0) e = 0;
        }
        e_sm[which][k] = e;
        vrow[which][k] = src[e];
    }
    __syncthreads();
#pragma unroll
    for (int i = tid; i < 256; i += 128) {
        int which = i >> 7, r = i & 127, k = r >> 3, h = r & 7;
        s_sm[which][k][h] = scores[(size_t)e_sm[which][k] * 8 + h];
    }
    __syncthreads();
    if (tid < 16) {
        int which = tid >> 3, h = tid & 7;
        float mx = -1e30f;
#pragma unroll
        for (int k = 0; k < 16; k++) mx = fmaxf(mx, s_sm[which][k][h]);
        float ex[16], se = 0.0f;
#pragma unroll
        for (int k = 0; k < 16; k++) { ex[k] = __expf(s_sm[which][k][h] - mx); se += ex[k]; }
        float inv = 1.0f / se;
#pragma unroll
        for (int k = 0; k < 16; k++) w_sm[which][k][h] = ex[k] * inv;
    }
    __syncthreads();

    int which = tid >> 6, lt = tid & 63, dd = lt * 2, h = dd >> 4;
    int n = base_n + which;
    if (n < N) {
        float a0 = 0.0f, a1 = 0.0f;
#pragma unroll
        for (int k = 0; k < 16; k++) {
            uint32_t u = *reinterpret_cast<const uint32_t*>(
                qkv + (size_t)vrow[which][k] * 384 + 256 + dd);
            float2 f = __bfloat1622float2(*reinterpret_cast<__nv_bfloat162*>(&u));
            float w = w_sm[which][k][h];
            a0 = fmaf(w, f.x, a0);
            a1 = fmaf(w, f.y, a1);
        }
        *reinterpret_cast<__nv_bfloat162*>(attn + (size_t)n * 128 + dd) =
            __floats2bfloat162_rn(a0, a1);
    }
}

// ---------------------------------------------------------------------------
// Host launcher
// ---------------------------------------------------------------------------
extern "C" void kernel_launch(void* const* d_in, const int* in_sizes, int n_in,
                              void* d_out, int out_size)
{
    const float* triplet   = (const float*)d_in[0];
    const int*   src       = (const int*)  d_in[2];
    const int*   dst       = (const int*)  d_in[3];
    const float* edge_bias = (const float*)d_in[4];
    const int*   inc_idx   = (const int*)  d_in[6];
    const float* ln1_g     = (const float*)d_in[8];
    const float* ln1_b     = (const float*)d_in[9];
    const float* qkv_w     = (const float*)d_in[10];
    const float* qkv_b     = (const float*)d_in[11];
    const float* res_in_w  = (const float*)d_in[12];
    const float* res_in_b  = (const float*)d_in[13];
    const float* res_ln_g  = (const float*)d_in[14];
    const float* res_ln_b  = (const float*)d_in[15];
    const float* ffn_in_w  = (const float*)d_in[16];
    const float* ffn_in_b  = (const float*)d_in[17];
    const float* ffn_out_w = (const float*)d_in[18];
    const float* ffn_out_b = (const float*)d_in[19];

    const int N = in_sizes[0] / 128;
    const int E = in_sizes[2];
    const int NT = (N + 127) / 128;

    __nv_bfloat16 *xln, *attn, *hid, *qkv, *wq, *wr, *w1, *w2;
    float *scores, *x2;
    cudaGetSymbolAddress((void**)&xln,    g_xln);
    cudaGetSymbolAddress((void**)&attn,   g_attn);
    cudaGetSymbolAddress((void**)&hid,    g_hid);
    cudaGetSymbolAddress((void**)&qkv,    g_qkv);
    cudaGetSymbolAddress((void**)&scores, g_scores);
    cudaGetSymbolAddress((void**)&x2,     g_x2);
    cudaGetSymbolAddress((void**)&wq,     g_wq);
    cudaGetSymbolAddress((void**)&wr,     g_wr);
    cudaGetSymbolAddress((void**)&w1,     g_w1);
    cudaGetSymbolAddress((void**)&w2,     g_w2);

    const int SMEM = 65536;
    cudaFuncSetAttribute(gemm_mma<0, 128, 128>, cudaFuncAttributeMaxDynamicSharedMemorySize, SMEM);
    cudaFuncSetAttribute(gemm_mma<1, 128, 128>, cudaFuncAttributeMaxDynamicSharedMemorySize, SMEM);
    cudaFuncSetAttribute(gemm_mma<2, 128, 128>, cudaFuncAttributeMaxDynamicSharedMemorySize, SMEM);
    cudaFuncSetAttribute(gemm_mma<3, 512, 64>,  cudaFuncAttributeMaxDynamicSharedMemorySize, SMEM);

    dim3 lnb(32, 8);
    int  lng = (N + 7) / 8;

    // 0) weight prep
    prep_weights<<<768, 256>>>(qkv_w, res_in_w, ffn_in_w, ffn_out_w, wq, wr, w1, w2);

    // 1) xln = LN(triplet_h)
    ln_kernel<<<lng, lnb>>>(triplet, ln1_g, ln1_b, xln, N);

    // 2) qkv = xln @ qkv_w + qkv_b
    gemm_mma<0, 128, 128><<<dim3(NT, 3), 256, SMEM>>>(xln, wq, qkv_b, nullptr, qkv, N);

    // 3) edge scores
    edge_scores_kernel<<<(E * 8 + 255) / 256, 256>>>(src, dst, edge_bias, qkv, scores, E);

    // 4) aggregation
    aggregate_kernel<<<(N + 1) / 2, 128>>>(inc_idx, src, scores, qkv, attn, N);

    // 5) x2 = triplet_h + attn @ res_in_w + res_in_b
    gemm_mma<1, 128, 128><<<dim3(NT, 1), 256, SMEM>>>(attn, wr, res_in_b, triplet, x2, N);

    // 6) xln = LN(x2)
    ln_kernel<<<lng, lnb>>>(x2, res_ln_g, res_ln_b, xln, N);

    // 7) hid = gelu(xln @ ffn_in_w + ffn_in_b)
    gemm_mma<2, 128, 128><<<dim3(NT, 4), 256, SMEM>>>(xln, w1, ffn_in_b, nullptr, hid, N);

    // 8) out = x2 + hid @ ffn_out_w + ffn_out_b
    gemm_mma<3, 512, 64><<<dim3(NT, 1), 256, SMEM>>>(hid, w2, ffn_out_b, x2, d_out, N);
}